// round 15
// baseline (speedup 1.0000x reference)
#include <cuda_runtime.h>
#include <cuda_bf16.h>
#include <math.h>

#define NNODES 50000
#define NPAD   50048              // 391 * 128
#define NEDGES 800000
#define ETOT   (NEDGES + NNODES)  // edges + self loops
#define BATCH  128
#define DIM    128
#define NEG_SLOPE 0.2f
#define NCHUNK 196                // ceil(50000/256)

// pair-packed word index within a 128-k row (fragment order for tf32 mma)
#define WIDX(k) (((k) & ~31) + (((k) & 3) << 3) + (((k) & 31) >> 2))

// ---------------- scratch (device globals) ----------------------------------
__device__ float    g_hA[NPAD * DIM];
__device__ float    g_hB[NPAD * DIM];
__device__ unsigned g_hT[NPAD * DIM];          // tf32 h, pair-packed per row
__device__ unsigned g_WT[2 * DIM * DIM];       // tf32 W, [n][k] pair-packed
__device__ __nv_bfloat16 g_xlh[(size_t)NPAD * 2 * DIM];  // bf16 xl (gather operand)
__device__ float    g_asrc[NPAD * 2];
__device__ float    g_adst[NPAD * 2];
__device__ int      g_deg[NNODES];
__device__ int      g_rowptr[NNODES + 1];
__device__ int      g_wp[NNODES];
__device__ int      g_col[ETOT];
__device__ int      g_bsum[256];
__device__ int      g_bbase[256];
__device__ int      g_bptr[BATCH + 1];
__device__ float    g_qstar[BATCH * 2 * DIM];
__device__ float    g_lq[BATCH * DIM];
__device__ float    g_lc[BATCH * DIM];

// ---------------- helpers ---------------------------------------------------
__device__ __forceinline__ float wred_sum(float v) {
#pragma unroll
    for (int o = 16; o > 0; o >>= 1) v += __shfl_xor_sync(0xffffffffu, v, o);
    return v;
}
__device__ __forceinline__ float lrelu(float v) { return v > 0.f ? v : NEG_SLOPE * v; }
__device__ __forceinline__ unsigned f2tf32(float f) {
    unsigned u;
    asm("cvt.rna.tf32.f32 %0, %1;" : "=r"(u) : "f"(f));
    return u;
}

// ---------------- input padding + deg init + tf32 pair-packed copy -----------
__global__ void k_init_h(const float* __restrict__ x) {
    int i = blockIdx.x * blockDim.x + threadIdx.x;  // float4 index
    if (i >= NPAD * (DIM / 4)) return;
    int n = i >> 5;
    int k = (i & 31) * 4;
    float4 v = make_float4(0.f, 0.f, 0.f, 0.f);
    if (n < NNODES) {
        if (k + 0 < 9) v.x = x[n * 9 + k + 0];
        if (k + 1 < 9) v.y = x[n * 9 + k + 1];
        if (k + 2 < 9) v.z = x[n * 9 + k + 2];
        if (k + 3 < 9) v.w = x[n * 9 + k + 3];
        if ((i & 31) == 0) g_deg[n] = 1;  // self loop
    }
    reinterpret_cast<float4*>(g_hA)[i] = v;
    int base = n * 128 + (k & ~31) + ((k & 31) >> 2);   // k%4==0
    g_hT[base + 0]  = f2tf32(v.x);
    g_hT[base + 8]  = f2tf32(v.y);
    g_hT[base + 16] = f2tf32(v.z);
    g_hT[base + 24] = f2tf32(v.w);
}

// W tf32 convert + Set2Set state zero (merged elementwise setup)
__global__ void k_misc(const float* __restrict__ W) {
    int i = blockIdx.x * blockDim.x + threadIdx.x;
    if (i < DIM * 2 * DIM) {
        int k = i >> 8;
        int n = i & 255;
        g_WT[n * 128 + WIDX(k)] = f2tf32(W[i]);
    }
    if (i < BATCH * 256) g_qstar[i] = 0.f;
    else if (i < BATCH * 256 + BATCH * 128) g_lq[i - BATCH * 256] = 0.f;
    else if (i < BATCH * 256 + 2 * BATCH * 128) g_lc[i - BATCH * 256 - BATCH * 128] = 0.f;
}

// ---------------- CSR build --------------------------------------------------
__global__ void k_hist(const int* __restrict__ dst) {
    int e = blockIdx.x * blockDim.x + threadIdx.x;
    if (e < NEDGES) atomicAdd(&g_deg[dst[e]], 1);
}
__global__ void __launch_bounds__(256) k_scan1() {
    __shared__ int ss[256];
    int t = threadIdx.x;
    int idx = blockIdx.x * 256 + t;
    ss[t] = (idx < NNODES) ? g_deg[idx] : 0;
    __syncthreads();
    for (int off = 128; off > 0; off >>= 1) {
        if (t < off) ss[t] += ss[t + off];
        __syncthreads();
    }
    if (t == 0) g_bsum[blockIdx.x] = ss[0];
}
__global__ void __launch_bounds__(256) k_scan2() {
    __shared__ int ss[256];
    int t = threadIdx.x;
    int v = (t < NCHUNK) ? g_bsum[t] : 0;
    ss[t] = v;
    __syncthreads();
    for (int off = 1; off < 256; off <<= 1) {
        int x = (t >= off) ? ss[t - off] : 0;
        __syncthreads();
        ss[t] += x;
        __syncthreads();
    }
    if (t < NCHUNK) g_bbase[t] = ss[t] - v;  // exclusive
}
__global__ void __launch_bounds__(256) k_scan3() {
    __shared__ int ss[256];
    int t = threadIdx.x;
    int idx = blockIdx.x * 256 + t;
    int v = (idx < NNODES) ? g_deg[idx] : 0;
    ss[t] = v;
    __syncthreads();
    for (int off = 1; off < 256; off <<= 1) {
        int x = (t >= off) ? ss[t - off] : 0;
        __syncthreads();
        ss[t] += x;
        __syncthreads();
    }
    if (idx < NNODES) {
        int r = g_bbase[blockIdx.x] + ss[t] - v;
        g_rowptr[idx] = r;
        g_wp[idx] = r;
    }
    if (idx == 0) g_rowptr[NNODES] = ETOT;
}
__global__ void k_scatter(const int* __restrict__ src, const int* __restrict__ dst) {
    int i = blockIdx.x * blockDim.x + threadIdx.x;
    if (i < NEDGES) {
        int d = dst[i];
        int p = atomicAdd(&g_wp[d], 1);
        g_col[p] = src[i];
    } else if (i < ETOT) {
        int n = i - NEDGES;
        int p = atomicAdd(&g_wp[n], 1);
        g_col[p] = n;
    }
}
__global__ void k_bptr(const int* __restrict__ batch) {
    int b = threadIdx.x;
    if (b > BATCH) return;
    if (b == BATCH) { g_bptr[BATCH] = NNODES; return; }
    int lo = 0, hi = NNODES;
    while (lo < hi) {
        int mid = (lo + hi) >> 1;
        if (batch[mid] < b) lo = mid + 1; else hi = mid;
    }
    g_bptr[b] = lo;
}

// ---- tf32 MMA GEMM + fused attention dots -----------------------------------
__global__ void __launch_bounds__(256) k_gemm_att(const float* __restrict__ att_src,
                                                  const float* __restrict__ att_dst,
                                                  int keff) {
    __shared__ unsigned Asw[128 * 34];    // 17 uint2 per row + pad
    __shared__ unsigned Bsw[128 * 34];
    __shared__ float sAs[128], sAd[128];

    const int tid = threadIdx.x;
    const int bm = blockIdx.x * 128;
    const int head = blockIdx.y;         // 0 or 1
    const int bn = head * 128;
    const int wid = tid >> 5, lane = tid & 31;
    const int wm = wid >> 2, wn = wid & 3;   // warp grid 2 x 4
    const int g = lane >> 2, tig = lane & 3;

    if (tid < 128) { sAs[tid] = 0.f; sAd[tid] = 0.f; }

    float c[4][4][4];
#pragma unroll
    for (int mt = 0; mt < 4; mt++)
#pragma unroll
        for (int nt = 0; nt < 4; nt++)
#pragma unroll
            for (int j = 0; j < 4; j++) c[mt][nt][j] = 0.f;

    for (int k0 = 0; k0 < keff; k0 += 32) {
#pragma unroll
        for (int i = 0; i < 4; i++) {
            int slot = tid + i * 256;
            int r = slot >> 3, q4 = (slot & 7) * 4;
            uint4 va = *reinterpret_cast<const uint4*>(g_hT + (size_t)(bm + r) * 128 + k0 + q4);
            uint2* pa = reinterpret_cast<uint2*>(&Asw[r * 34 + q4]);
            pa[0] = make_uint2(va.x, va.y);
            pa[1] = make_uint2(va.z, va.w);
            uint4 vb = *reinterpret_cast<const uint4*>(g_WT + (size_t)(bn + r) * 128 + k0 + q4);
            uint2* pb = reinterpret_cast<uint2*>(&Bsw[r * 34 + q4]);
            pb[0] = make_uint2(vb.x, vb.y);
            pb[1] = make_uint2(vb.z, vb.w);
        }
        __syncthreads();
        const uint2* AsP = reinterpret_cast<const uint2*>(Asw);
        const uint2* BsP = reinterpret_cast<const uint2*>(Bsw);
#pragma unroll
        for (int ks = 0; ks < 4; ks++) {
            unsigned af[4][4], bf[4][2];
#pragma unroll
            for (int mt = 0; mt < 4; mt++) {
                int r0 = wm * 64 + mt * 16 + g;
                uint2 lo = AsP[r0 * 17 + tig * 4 + ks];
                uint2 hi = AsP[(r0 + 8) * 17 + tig * 4 + ks];
                af[mt][0] = lo.x; af[mt][1] = hi.x;
                af[mt][2] = lo.y; af[mt][3] = hi.y;
            }
#pragma unroll
            for (int nt = 0; nt < 4; nt++) {
                int c0 = wn * 32 + nt * 8 + g;
                uint2 bp = BsP[c0 * 17 + tig * 4 + ks];
                bf[nt][0] = bp.x; bf[nt][1] = bp.y;
            }
#pragma unroll
            for (int mt = 0; mt < 4; mt++)
#pragma unroll
                for (int nt = 0; nt < 4; nt++) {
                    asm volatile(
                        "mma.sync.aligned.m16n8k8.row.col.f32.tf32.tf32.f32 "
                        "{%0,%1,%2,%3}, {%4,%5,%6,%7}, {%8,%9}, {%0,%1,%2,%3};"
                        : "+f"(c[mt][nt][0]), "+f"(c[mt][nt][1]),
                          "+f"(c[mt][nt][2]), "+f"(c[mt][nt][3])
                        : "r"(af[mt][0]), "r"(af[mt][1]), "r"(af[mt][2]), "r"(af[mt][3]),
                          "r"(bf[nt][0]), "r"(bf[nt][1]));
                }
        }
        __syncthreads();
    }

    float asr[8], adr[8];
#pragma unroll
    for (int nt = 0; nt < 4; nt++) {
#pragma unroll
        for (int j = 0; j < 2; j++) {
            int col = wn * 32 + nt * 8 + tig * 2 + j;
            asr[nt * 2 + j] = att_src[head * 128 + col];
            adr[nt * 2 + j] = att_dst[head * 128 + col];
        }
    }

#pragma unroll
    for (int mt = 0; mt < 4; mt++) {
#pragma unroll
        for (int half = 0; half < 2; half++) {
            int lr = wm * 64 + mt * 16 + g + half * 8;
            int row = bm + lr;
            float ds = 0.f, dd = 0.f;
#pragma unroll
            for (int nt = 0; nt < 4; nt++) {
                float v0 = c[mt][nt][half * 2];
                float v1 = c[mt][nt][half * 2 + 1];
                int col = bn + wn * 32 + nt * 8 + tig * 2;
                *reinterpret_cast<__nv_bfloat162*>(g_xlh + (size_t)row * 256 + col) =
                    __floats2bfloat162_rn(v0, v1);
                ds += v0 * asr[nt * 2] + v1 * asr[nt * 2 + 1];
                dd += v0 * adr[nt * 2] + v1 * adr[nt * 2 + 1];
            }
            ds += __shfl_xor_sync(0xffffffffu, ds, 1);
            ds += __shfl_xor_sync(0xffffffffu, ds, 2);
            dd += __shfl_xor_sync(0xffffffffu, dd, 1);
            dd += __shfl_xor_sync(0xffffffffu, dd, 2);
            if (tig == 0) {
                atomicAdd(&sAs[lr], ds);
                atomicAdd(&sAd[lr], dd);
            }
        }
    }
    __syncthreads();
    if (tid < 128) {
        g_asrc[(size_t)(bm + tid) * 2 + head] = sAs[tid];
        g_adst[(size_t)(bm + tid) * 2 + head] = sAd[tid];
    }
}

// ------- softmax-aggregate: warp per (node, head); single fused pass ---------
// Weight computed inline (uniform across warp: g_asrc broadcast + redundant
// exp); sum accumulated alongside the weighted gather; normalize at the end.
__global__ void __launch_bounds__(256) k_aggregate(const float* __restrict__ bias,
                                                   float* __restrict__ out) {
    __shared__ float stage[4][DIM];

    const int tid = threadIdx.x;
    const int wid = tid >> 5, lane = tid & 31;
    const int pairId = wid >> 1;
    const int head = wid & 1;
    const int node = blockIdx.x * 4 + pairId;
    const bool active = node < NNODES;

    int p0 = 0, L = 0;
    float ad = 0.f;
    if (active) {
        p0 = g_rowptr[node];
        L = g_rowptr[node + 1] - p0;
        ad = g_adst[node * 2 + head];
    }

    float s = 0.f;
    float4 a = make_float4(0.f, 0.f, 0.f, 0.f);
    if (active) {
        const __nv_bfloat16* xb = g_xlh + head * 128;
        int q = 0;
        for (; q + 4 <= L; q += 4) {
            int si0 = g_col[p0 + q + 0];
            int si1 = g_col[p0 + q + 1];
            int si2 = g_col[p0 + q + 2];
            int si3 = g_col[p0 + q + 3];
            // attention scalars: uniform address across warp -> broadcast loads
            float e0 = g_asrc[si0 * 2 + head];
            float e1 = g_asrc[si1 * 2 + head];
            float e2 = g_asrc[si2 * 2 + head];
            float e3 = g_asrc[si3 * 2 + head];
            // feature rows: 4 independent 256B loads in flight
            uint2 u0 = *reinterpret_cast<const uint2*>(xb + (size_t)si0 * 256 + lane * 4);
            uint2 u1 = *reinterpret_cast<const uint2*>(xb + (size_t)si1 * 256 + lane * 4);
            uint2 u2 = *reinterpret_cast<const uint2*>(xb + (size_t)si2 * 256 + lane * 4);
            uint2 u3 = *reinterpret_cast<const uint2*>(xb + (size_t)si3 * 256 + lane * 4);
            float w0 = __expf(lrelu(e0 + ad));
            float w1 = __expf(lrelu(e1 + ad));
            float w2 = __expf(lrelu(e2 + ad));
            float w3 = __expf(lrelu(e3 + ad));
            s += w0 + w1 + w2 + w3;
            float2 f0a = __bfloat1622float2(*reinterpret_cast<__nv_bfloat162*>(&u0.x));
            float2 f0b = __bfloat1622float2(*reinterpret_cast<__nv_bfloat162*>(&u0.y));
            float2 f1a = __bfloat1622float2(*reinterpret_cast<__nv_bfloat162*>(&u1.x));
            float2 f1b = __bfloat1622float2(*reinterpret_cast<__nv_bfloat162*>(&u1.y));
            float2 f2a = __bfloat1622float2(*reinterpret_cast<__nv_bfloat162*>(&u2.x));
            float2 f2b = __bfloat1622float2(*reinterpret_cast<__nv_bfloat162*>(&u2.y));
            float2 f3a = __bfloat1622float2(*reinterpret_cast<__nv_bfloat162*>(&u3.x));
            float2 f3b = __bfloat1622float2(*reinterpret_cast<__nv_bfloat162*>(&u3.y));
            a.x += w0 * f0a.x; a.y += w0 * f0a.y; a.z += w0 * f0b.x; a.w += w0 * f0b.y;
            a.x += w1 * f1a.x; a.y += w1 * f1a.y; a.z += w1 * f1b.x; a.w += w1 * f1b.y;
            a.x += w2 * f2a.x; a.y += w2 * f2a.y; a.z += w2 * f2b.x; a.w += w2 * f2b.y;
            a.x += w3 * f3a.x; a.y += w3 * f3a.y; a.z += w3 * f3b.x; a.w += w3 * f3b.y;
        }
        for (; q < L; q++) {
            int si = g_col[p0 + q];
            float w = __expf(lrelu(g_asrc[si * 2 + head] + ad));
            uint2 u = *reinterpret_cast<const uint2*>(xb + (size_t)si * 256 + lane * 4);
            s += w;
            float2 fa = __bfloat1622float2(*reinterpret_cast<__nv_bfloat162*>(&u.x));
            float2 fb = __bfloat1622float2(*reinterpret_cast<__nv_bfloat162*>(&u.y));
            a.x += w * fa.x; a.y += w * fa.y; a.z += w * fb.x; a.w += w * fb.y;
        }
    }
    float inv = 1.f / (s + 1e-16f);

    if (active && head == 1) {
        *reinterpret_cast<float4*>(&stage[pairId][lane * 4]) =
            make_float4(a.x * inv, a.y * inv, a.z * inv, a.w * inv);
    }
    __syncthreads();
    if (active && head == 0) {
        float4 v1 = *reinterpret_cast<const float4*>(&stage[pairId][lane * 4]);
        float4 bv = reinterpret_cast<const float4*>(bias)[lane];
        float4 o;
        o.x = 0.5f * (a.x * inv + v1.x) + bv.x;
        o.y = 0.5f * (a.y * inv + v1.y) + bv.y;
        o.z = 0.5f * (a.z * inv + v1.z) + bv.z;
        o.w = 0.5f * (a.w * inv + v1.w) + bv.w;
        *reinterpret_cast<float4*>(out + (size_t)node * DIM + lane * 4) = o;
        int k = lane * 4;
        int base = node * 128 + (k & ~31) + ((k & 31) >> 2);
        g_hT[base + 0]  = f2tf32(o.x);
        g_hT[base + 8]  = f2tf32(o.y);
        g_hT[base + 16] = f2tf32(o.z);
        g_hT[base + 24] = f2tf32(o.w);
    }
}

// ---------------- Set2Set ----------------------------------------------------
__global__ void __launch_bounds__(512) k_lstm(const float* __restrict__ Wih,
                                              const float* __restrict__ Whh,
                                              const float* __restrict__ bih,
                                              const float* __restrict__ bhh) {
    int b = blockIdx.x;
    int tid = threadIdx.x;
    __shared__ float qs[256];
    __shared__ float hs[128];
    __shared__ float gates[512];
    if (tid < 256) qs[tid] = g_qstar[b * 256 + tid];
    else if (tid < 384) hs[tid - 256] = g_lq[b * 128 + (tid - 256)];
    __syncthreads();
    float acc = bih[tid] + bhh[tid];
    const float4* wi = reinterpret_cast<const float4*>(Wih + (size_t)tid * 256);
#pragma unroll 8
    for (int k = 0; k < 64; k++) {
        float4 w = wi[k];
        acc += w.x * qs[k * 4] + w.y * qs[k * 4 + 1] + w.z * qs[k * 4 + 2] + w.w * qs[k * 4 + 3];
    }
    const float4* wh = reinterpret_cast<const float4*>(Whh + (size_t)tid * 128);
#pragma unroll 8
    for (int k = 0; k < 32; k++) {
        float4 w = wh[k];
        acc += w.x * hs[k * 4] + w.y * hs[k * 4 + 1] + w.z * hs[k * 4 + 2] + w.w * hs[k * 4 + 3];
    }
    gates[tid] = acc;
    __syncthreads();
    if (tid < 128) {
        float gi = 1.f / (1.f + __expf(-gates[tid]));
        float gf = 1.f / (1.f + __expf(-gates[128 + tid]));
        float gg = tanhf(gates[256 + tid]);
        float go = 1.f / (1.f + __expf(-gates[384 + tid]));
        float c2 = gf * g_lc[b * 128 + tid] + gi * gg;
        float q = go * tanhf(c2);
        g_lc[b * 128 + tid] = c2;
        g_lq[b * 128 + tid] = q;
        g_qstar[b * 256 + tid] = q;
    }
}

// fused attention-pool step (512 threads / 16 warps)
__global__ void __launch_bounds__(512) k_s2s(const float* __restrict__ h) {
    int b = blockIdx.x;
    int tid = threadIdx.x;
    int wid = tid >> 5, lane = tid & 31;
    int p0 = g_bptr[b];
    int L = g_bptr[b + 1] - p0;

    __shared__ float q[128];
    __shared__ float se[1024];
    __shared__ float red[40];
    __shared__ float racc[512];

    if (tid < 128) q[tid] = g_lq[b * 128 + tid];
    __syncthreads();

    float4 qv = reinterpret_cast<const float4*>(q)[lane];
    for (int i = wid; i < L; i += 16) {
        float4 hv = reinterpret_cast<const float4*>(h + (size_t)(p0 + i) * 128)[lane];
        float r = hv.x * qv.x + hv.y * qv.y + hv.z * qv.z + hv.w * qv.w;
        r = wred_sum(r);
        if (lane == 0) se[i] = r;
    }
    __syncthreads();

    float m = -1e30f;
    for (int i = tid; i < L; i += 512) m = fmaxf(m, se[i]);
#pragma unroll
    for (int o = 16; o > 0; o >>= 1) m = fmaxf(m, __shfl_xor_sync(0xffffffffu, m, o));
    if (lane == 0) red[wid] = m;
    __syncthreads();
    if (tid == 0) {
        float mm = red[0];
        for (int w = 1; w < 16; w++) mm = fmaxf(mm, red[w]);
        red[32] = mm;
    }
    __syncthreads();
    m = red[32];

    float s = 0.f;
    for (int i = tid; i < L; i += 512) {
        float w = __expf(se[i] - m);
        se[i] = w;
        s += w;
    }
    s = wred_sum(s);
    if (lane == 0) red[wid] = s;
    __syncthreads();
    if (tid == 0) {
        float ss = 0.f;
        for (int w = 0; w < 16; w++) ss += red[w];
        red[33] = 1.f / (ss + 1e-16f);
    }
    __syncthreads();
    float inv = red[33];

    int d = tid & 127, part = tid >> 7;
    float acc = 0.f;
    for (int i = part; i < L; i += 4)
        acc += se[i] * h[(size_t)(p0 + i) * 128 + d];
    racc[tid] = acc;
    __syncthreads();
    if (tid < 128)
        g_qstar[b * 256 + 128 + tid] =
            (racc[tid] + racc[128 + tid] + racc[256 + tid] + racc[384 + tid]) * inv;
}

// ---------------- final MLP --------------------------------------------------
__global__ void __launch_bounds__(128) k_mlp(const float* __restrict__ W1, const float* __restrict__ b1,
                                             const float* __restrict__ W2, const float* __restrict__ b2,
                                             float* __restrict__ out) {
    int b = blockIdx.x;
    int j = threadIdx.x;
    __shared__ float qs[256];
    __shared__ float hid[128];
    qs[j] = g_qstar[b * 256 + j];
    qs[128 + j] = g_qstar[b * 256 + 128 + j];
    __syncthreads();
    float acc = b1[j];
#pragma unroll 8
    for (int k = 0; k < 256; k++) acc += qs[k] * W1[k * 128 + j];
    hid[j] = fmaxf(acc, 0.f);
    __syncthreads();
    float acc2 = b2[j];
#pragma unroll 8
    for (int k = 0; k < 128; k++) acc2 += hid[k] * W2[k * 128 + j];
    out[b * 128 + j] = acc2;
}

// ---------------- launch -----------------------------------------------------
extern "C" void kernel_launch(void* const* d_in, const int* in_sizes, int n_in,
                              void* d_out, int out_size) {
    const float* x        = (const float*)d_in[0];
    const int*   ei       = (const int*)d_in[1];     // int64 inputs delivered as int32
    const int*   batch    = (const int*)d_in[3];
    const float* gat_W    = (const float*)d_in[4];
    const float* att_src  = (const float*)d_in[5];
    const float* att_dst  = (const float*)d_in[6];
    const float* gat_bias = (const float*)d_in[7];
    const float* Wih      = (const float*)d_in[8];
    const float* Whh      = (const float*)d_in[9];
    const float* bih      = (const float*)d_in[10];
    const float* bhh      = (const float*)d_in[11];
    const float* W1       = (const float*)d_in[12];
    const float* b1       = (const float*)d_in[13];
    const float* W2       = (const float*)d_in[14];
    const float* b2       = (const float*)d_in[15];
    float*       out      = (float*)d_out;

    const int* src = ei;
    const int* dst = ei + NEDGES;

    float* hA = nullptr;
    float* hB = nullptr;
    cudaGetSymbolAddress((void**)&hA, g_hA);
    cudaGetSymbolAddress((void**)&hB, g_hB);

    const int aggBlocks = (NNODES + 3) / 4;
    dim3 gg(NPAD / 128, 2);

    // order keeps k_gemm_att at launch #4 (ncu fixed-window profiling)
    k_init_h<<<(NPAD * (DIM / 4) + 255) / 256, 256>>>(x);
    k_misc<<<256, 256>>>(gat_W);
    k_hist<<<(NEDGES + 255) / 256, 256>>>(dst);
    k_gemm_att<<<gg, 256>>>(att_src, att_dst, 32);        // conv0 GEMM: 9 nonzero feats
    k_scan1<<<NCHUNK, 256>>>();
    k_scan2<<<1, 256>>>();
    k_scan3<<<NCHUNK, 256>>>();
    k_scatter<<<(ETOT + 255) / 256, 256>>>(src, dst);
    k_bptr<<<1, 256>>>(batch);

    float* cur = hA;
    float* nxt = hB;
    for (int c = 0; c < 3; c++) {
        if (c > 0) k_gemm_att<<<gg, 256>>>(att_src, att_dst, 128);
        k_aggregate<<<aggBlocks, 256>>>(gat_bias, nxt);
        float* t = cur; cur = nxt; nxt = t;
    }

    for (int s = 0; s < 3; s++) {
        k_lstm<<<BATCH, 512>>>(Wih, Whh, bih, bhh);
        k_s2s<<<BATCH, 512>>>(cur);
    }

    k_mlp<<<BATCH, 128>>>(W1, b1, W2, b2, out);
}

// round 16
// speedup vs baseline: 1.1870x; 1.1870x over previous
#include <cuda_runtime.h>
#include <cuda_bf16.h>
#include <math.h>

#define NNODES 50000
#define NPAD   50048              // 391 * 128
#define NEDGES 800000
#define ETOT   (NEDGES + NNODES)  // edges + self loops
#define BATCH  128
#define DIM    128
#define NEG_SLOPE 0.2f
#define NCHUNK 196                // ceil(50000/256)
#define CAP    128                // smem weight stash per warp

// pair-packed word index within a 128-k row (fragment order for tf32 mma)
#define WIDX(k) (((k) & ~31) + (((k) & 3) << 3) + (((k) & 31) >> 2))

// ---------------- scratch (device globals) ----------------------------------
__device__ float    g_hA[NPAD * DIM];
__device__ float    g_hB[NPAD * DIM];
__device__ unsigned g_hT[NPAD * DIM];          // tf32 h, pair-packed per row
__device__ unsigned g_WT[2 * DIM * DIM];       // tf32 W, [n][k] pair-packed
__device__ __nv_bfloat16 g_xlh[(size_t)NPAD * 2 * DIM];  // bf16 xl (gather operand)
__device__ float    g_asrc[NPAD * 2];
__device__ float    g_adst[NPAD * 2];
__device__ int      g_deg[NNODES];
__device__ int      g_rowptr[NNODES + 1];
__device__ int      g_wp[NNODES];
__device__ int      g_col[ETOT];
__device__ float    g_ew[(size_t)2 * ETOT];    // [head][edge] fallback
__device__ int      g_bsum[256];
__device__ int      g_bbase[256];
__device__ int      g_bptr[BATCH + 1];
__device__ float    g_qstar[BATCH * 2 * DIM];
__device__ float    g_lq[BATCH * DIM];
__device__ float    g_lc[BATCH * DIM];
__device__ float    g_WihT[4 * DIM * 2 * DIM]; // interleaved-4: [kq][j][4]
__device__ float    g_WhhT[4 * DIM * DIM];     // interleaved-4: [kq][j][4]

// ---------------- helpers ---------------------------------------------------
__device__ __forceinline__ float wred_sum(float v) {
#pragma unroll
    for (int o = 16; o > 0; o >>= 1) v += __shfl_xor_sync(0xffffffffu, v, o);
    return v;
}
__device__ __forceinline__ float lrelu(float v) { return v > 0.f ? v : NEG_SLOPE * v; }
__device__ __forceinline__ unsigned f2tf32(float f) {
    unsigned u;
    asm("cvt.rna.tf32.f32 %0, %1;" : "=r"(u) : "f"(f));
    return u;
}

// ---------------- input padding + deg init + tf32 pair-packed copy -----------
__global__ void k_init_h(const float* __restrict__ x) {
    int i = blockIdx.x * blockDim.x + threadIdx.x;  // float4 index
    if (i >= NPAD * (DIM / 4)) return;
    int n = i >> 5;
    int k = (i & 31) * 4;
    float4 v = make_float4(0.f, 0.f, 0.f, 0.f);
    if (n < NNODES) {
        if (k + 0 < 9) v.x = x[n * 9 + k + 0];
        if (k + 1 < 9) v.y = x[n * 9 + k + 1];
        if (k + 2 < 9) v.z = x[n * 9 + k + 2];
        if (k + 3 < 9) v.w = x[n * 9 + k + 3];
        if ((i & 31) == 0) g_deg[n] = 1;  // self loop
    }
    reinterpret_cast<float4*>(g_hA)[i] = v;
    int base = n * 128 + (k & ~31) + ((k & 31) >> 2);   // k%4==0
    g_hT[base + 0]  = f2tf32(v.x);
    g_hT[base + 8]  = f2tf32(v.y);
    g_hT[base + 16] = f2tf32(v.z);
    g_hT[base + 24] = f2tf32(v.w);
}

// W tf32 convert + LSTM weight interleave + Set2Set state zero (merged setup)
// launched with >= 131072 threads
__global__ void k_misc(const float* __restrict__ W,
                       const float* __restrict__ Wih,
                       const float* __restrict__ Whh) {
    int i = blockIdx.x * blockDim.x + threadIdx.x;
    if (i < DIM * 2 * DIM) {                    // gat_W -> tf32 pair-packed
        int k = i >> 8;
        int n = i & 255;
        g_WT[n * 128 + WIDX(k)] = f2tf32(W[i]);
    }
    if (i < 4 * DIM * 2 * DIM) {                // Wih [512][256] -> [kq][j][4]
        int j = i >> 8;
        int k = i & 255;
        g_WihT[(k >> 2) * 2048 + j * 4 + (k & 3)] = Wih[i];
    }
    if (i < 4 * DIM * DIM) {                    // Whh [512][128] -> [kq][j][4]
        int j = i >> 7;
        int k = i & 127;
        g_WhhT[(k >> 2) * 2048 + j * 4 + (k & 3)] = Whh[i];
    }
    if (i < BATCH * 256) g_qstar[i] = 0.f;
    else if (i < BATCH * 256 + BATCH * 128) g_lq[i - BATCH * 256] = 0.f;
    else if (i < BATCH * 256 + 2 * BATCH * 128) g_lc[i - BATCH * 256 - BATCH * 128] = 0.f;
}

// ---------------- CSR build --------------------------------------------------
__global__ void k_hist(const int* __restrict__ dst) {
    int e = blockIdx.x * blockDim.x + threadIdx.x;
    if (e < NEDGES) atomicAdd(&g_deg[dst[e]], 1);
}
__global__ void __launch_bounds__(256) k_scan1() {
    __shared__ int ss[256];
    int t = threadIdx.x;
    int idx = blockIdx.x * 256 + t;
    ss[t] = (idx < NNODES) ? g_deg[idx] : 0;
    __syncthreads();
    for (int off = 128; off > 0; off >>= 1) {
        if (t < off) ss[t] += ss[t + off];
        __syncthreads();
    }
    if (t == 0) g_bsum[blockIdx.x] = ss[0];
}
__global__ void __launch_bounds__(256) k_scan2() {
    __shared__ int ss[256];
    int t = threadIdx.x;
    int v = (t < NCHUNK) ? g_bsum[t] : 0;
    ss[t] = v;
    __syncthreads();
    for (int off = 1; off < 256; off <<= 1) {
        int x = (t >= off) ? ss[t - off] : 0;
        __syncthreads();
        ss[t] += x;
        __syncthreads();
    }
    if (t < NCHUNK) g_bbase[t] = ss[t] - v;  // exclusive
}
__global__ void __launch_bounds__(256) k_scan3() {
    __shared__ int ss[256];
    int t = threadIdx.x;
    int idx = blockIdx.x * 256 + t;
    int v = (idx < NNODES) ? g_deg[idx] : 0;
    ss[t] = v;
    __syncthreads();
    for (int off = 1; off < 256; off <<= 1) {
        int x = (t >= off) ? ss[t - off] : 0;
        __syncthreads();
        ss[t] += x;
        __syncthreads();
    }
    if (idx < NNODES) {
        int r = g_bbase[blockIdx.x] + ss[t] - v;
        g_rowptr[idx] = r;
        g_wp[idx] = r;
    }
    if (idx == 0) g_rowptr[NNODES] = ETOT;
}
__global__ void k_scatter(const int* __restrict__ src, const int* __restrict__ dst) {
    int i = blockIdx.x * blockDim.x + threadIdx.x;
    if (i < NEDGES) {
        int d = dst[i];
        int p = atomicAdd(&g_wp[d], 1);
        g_col[p] = src[i];
    } else if (i < ETOT) {
        int n = i - NEDGES;
        int p = atomicAdd(&g_wp[n], 1);
        g_col[p] = n;
    }
}
__global__ void k_bptr(const int* __restrict__ batch) {
    int b = threadIdx.x;
    if (b > BATCH) return;
    if (b == BATCH) { g_bptr[BATCH] = NNODES; return; }
    int lo = 0, hi = NNODES;
    while (lo < hi) {
        int mid = (lo + hi) >> 1;
        if (batch[mid] < b) lo = mid + 1; else hi = mid;
    }
    g_bptr[b] = lo;
}

// ---- tf32 MMA GEMM + fused attention dots -----------------------------------
__global__ void __launch_bounds__(256) k_gemm_att(const float* __restrict__ att_src,
                                                  const float* __restrict__ att_dst,
                                                  int keff) {
    __shared__ unsigned Asw[128 * 34];    // 17 uint2 per row + pad
    __shared__ unsigned Bsw[128 * 34];
    __shared__ float sAs[128], sAd[128];

    const int tid = threadIdx.x;
    const int bm = blockIdx.x * 128;
    const int head = blockIdx.y;         // 0 or 1
    const int bn = head * 128;
    const int wid = tid >> 5, lane = tid & 31;
    const int wm = wid >> 2, wn = wid & 3;   // warp grid 2 x 4
    const int g = lane >> 2, tig = lane & 3;

    if (tid < 128) { sAs[tid] = 0.f; sAd[tid] = 0.f; }

    float c[4][4][4];
#pragma unroll
    for (int mt = 0; mt < 4; mt++)
#pragma unroll
        for (int nt = 0; nt < 4; nt++)
#pragma unroll
            for (int j = 0; j < 4; j++) c[mt][nt][j] = 0.f;

    for (int k0 = 0; k0 < keff; k0 += 32) {
#pragma unroll
        for (int i = 0; i < 4; i++) {
            int slot = tid + i * 256;
            int r = slot >> 3, q4 = (slot & 7) * 4;
            uint4 va = *reinterpret_cast<const uint4*>(g_hT + (size_t)(bm + r) * 128 + k0 + q4);
            uint2* pa = reinterpret_cast<uint2*>(&Asw[r * 34 + q4]);
            pa[0] = make_uint2(va.x, va.y);
            pa[1] = make_uint2(va.z, va.w);
            uint4 vb = *reinterpret_cast<const uint4*>(g_WT + (size_t)(bn + r) * 128 + k0 + q4);
            uint2* pb = reinterpret_cast<uint2*>(&Bsw[r * 34 + q4]);
            pb[0] = make_uint2(vb.x, vb.y);
            pb[1] = make_uint2(vb.z, vb.w);
        }
        __syncthreads();
        const uint2* AsP = reinterpret_cast<const uint2*>(Asw);
        const uint2* BsP = reinterpret_cast<const uint2*>(Bsw);
#pragma unroll
        for (int ks = 0; ks < 4; ks++) {
            unsigned af[4][4], bf[4][2];
#pragma unroll
            for (int mt = 0; mt < 4; mt++) {
                int r0 = wm * 64 + mt * 16 + g;
                uint2 lo = AsP[r0 * 17 + tig * 4 + ks];
                uint2 hi = AsP[(r0 + 8) * 17 + tig * 4 + ks];
                af[mt][0] = lo.x; af[mt][1] = hi.x;
                af[mt][2] = lo.y; af[mt][3] = hi.y;
            }
#pragma unroll
            for (int nt = 0; nt < 4; nt++) {
                int c0 = wn * 32 + nt * 8 + g;
                uint2 bp = BsP[c0 * 17 + tig * 4 + ks];
                bf[nt][0] = bp.x; bf[nt][1] = bp.y;
            }
#pragma unroll
            for (int mt = 0; mt < 4; mt++)
#pragma unroll
                for (int nt = 0; nt < 4; nt++) {
                    asm volatile(
                        "mma.sync.aligned.m16n8k8.row.col.f32.tf32.tf32.f32 "
                        "{%0,%1,%2,%3}, {%4,%5,%6,%7}, {%8,%9}, {%0,%1,%2,%3};"
                        : "+f"(c[mt][nt][0]), "+f"(c[mt][nt][1]),
                          "+f"(c[mt][nt][2]), "+f"(c[mt][nt][3])
                        : "r"(af[mt][0]), "r"(af[mt][1]), "r"(af[mt][2]), "r"(af[mt][3]),
                          "r"(bf[nt][0]), "r"(bf[nt][1]));
                }
        }
        __syncthreads();
    }

    float asr[8], adr[8];
#pragma unroll
    for (int nt = 0; nt < 4; nt++) {
#pragma unroll
        for (int j = 0; j < 2; j++) {
            int col = wn * 32 + nt * 8 + tig * 2 + j;
            asr[nt * 2 + j] = att_src[head * 128 + col];
            adr[nt * 2 + j] = att_dst[head * 128 + col];
        }
    }

#pragma unroll
    for (int mt = 0; mt < 4; mt++) {
#pragma unroll
        for (int half = 0; half < 2; half++) {
            int lr = wm * 64 + mt * 16 + g + half * 8;
            int row = bm + lr;
            float ds = 0.f, dd = 0.f;
#pragma unroll
            for (int nt = 0; nt < 4; nt++) {
                float v0 = c[mt][nt][half * 2];
                float v1 = c[mt][nt][half * 2 + 1];
                int col = bn + wn * 32 + nt * 8 + tig * 2;
                *reinterpret_cast<__nv_bfloat162*>(g_xlh + (size_t)row * 256 + col) =
                    __floats2bfloat162_rn(v0, v1);
                ds += v0 * asr[nt * 2] + v1 * asr[nt * 2 + 1];
                dd += v0 * adr[nt * 2] + v1 * adr[nt * 2 + 1];
            }
            ds += __shfl_xor_sync(0xffffffffu, ds, 1);
            ds += __shfl_xor_sync(0xffffffffu, ds, 2);
            dd += __shfl_xor_sync(0xffffffffu, dd, 1);
            dd += __shfl_xor_sync(0xffffffffu, dd, 2);
            if (tig == 0) {
                atomicAdd(&sAs[lr], ds);
                atomicAdd(&sAd[lr], dd);
            }
        }
    }
    __syncthreads();
    if (tid < 128) {
        g_asrc[(size_t)(bm + tid) * 2 + head] = sAs[tid];
        g_adst[(size_t)(bm + tid) * 2 + head] = sAd[tid];
    }
}

// ------- softmax-aggregate: warp per (node, head); 4-deep bf16 gather --------
// (R12/R14 two-pass version — proven fastest; out==nullptr skips fp32 store)
__global__ void __launch_bounds__(256) k_aggregate(const float* __restrict__ bias,
                                                   float* __restrict__ out) {
    __shared__ float wbuf[8][CAP];
    __shared__ float stage[4][DIM];

    const int tid = threadIdx.x;
    const int wid = tid >> 5, lane = tid & 31;
    const int pairId = wid >> 1;
    const int head = wid & 1;
    const int node = blockIdx.x * 4 + pairId;
    const bool active = node < NNODES;

    int p0 = 0, L = 0;
    float ad = 0.f;
    if (active) {
        p0 = g_rowptr[node];
        L = g_rowptr[node + 1] - p0;
        ad = g_adst[node * 2 + head];
    }
    const bool inCap = (L <= CAP);

    float s = 0.f;
    if (active) {
        if (inCap) {
            for (int q = lane; q < L; q += 32) {
                int si = g_col[p0 + q];
                float e = __expf(lrelu(g_asrc[si * 2 + head] + ad));
                wbuf[wid][q] = e;
                s += e;
            }
        } else {
            for (int q = lane; q < L; q += 32) {
                int si = g_col[p0 + q];
                float e = __expf(lrelu(g_asrc[si * 2 + head] + ad));
                g_ew[(size_t)head * ETOT + p0 + q] = e;
                s += e;
            }
        }
        s = wred_sum(s);
    }
    __syncwarp();
    float inv = 1.f / (s + 1e-16f);

    float4 a = make_float4(0.f, 0.f, 0.f, 0.f);
    if (active) {
        const __nv_bfloat16* xb = g_xlh + head * 128;
        int q = 0;
        for (; q + 4 <= L; q += 4) {
            int si0 = g_col[p0 + q + 0];
            int si1 = g_col[p0 + q + 1];
            int si2 = g_col[p0 + q + 2];
            int si3 = g_col[p0 + q + 3];
            uint2 u0 = *reinterpret_cast<const uint2*>(xb + (size_t)si0 * 256 + lane * 4);
            uint2 u1 = *reinterpret_cast<const uint2*>(xb + (size_t)si1 * 256 + lane * 4);
            uint2 u2 = *reinterpret_cast<const uint2*>(xb + (size_t)si2 * 256 + lane * 4);
            uint2 u3 = *reinterpret_cast<const uint2*>(xb + (size_t)si3 * 256 + lane * 4);
            float w0, w1, w2, w3;
            if (inCap) {
                w0 = wbuf[wid][q + 0]; w1 = wbuf[wid][q + 1];
                w2 = wbuf[wid][q + 2]; w3 = wbuf[wid][q + 3];
            } else {
                w0 = g_ew[(size_t)head * ETOT + p0 + q + 0];
                w1 = g_ew[(size_t)head * ETOT + p0 + q + 1];
                w2 = g_ew[(size_t)head * ETOT + p0 + q + 2];
                w3 = g_ew[(size_t)head * ETOT + p0 + q + 3];
            }
            float2 f0a = __bfloat1622float2(*reinterpret_cast<__nv_bfloat162*>(&u0.x));
            float2 f0b = __bfloat1622float2(*reinterpret_cast<__nv_bfloat162*>(&u0.y));
            float2 f1a = __bfloat1622float2(*reinterpret_cast<__nv_bfloat162*>(&u1.x));
            float2 f1b = __bfloat1622float2(*reinterpret_cast<__nv_bfloat162*>(&u1.y));
            float2 f2a = __bfloat1622float2(*reinterpret_cast<__nv_bfloat162*>(&u2.x));
            float2 f2b = __bfloat1622float2(*reinterpret_cast<__nv_bfloat162*>(&u2.y));
            float2 f3a = __bfloat1622float2(*reinterpret_cast<__nv_bfloat162*>(&u3.x));
            float2 f3b = __bfloat1622float2(*reinterpret_cast<__nv_bfloat162*>(&u3.y));
            a.x += w0 * f0a.x; a.y += w0 * f0a.y; a.z += w0 * f0b.x; a.w += w0 * f0b.y;
            a.x += w1 * f1a.x; a.y += w1 * f1a.y; a.z += w1 * f1b.x; a.w += w1 * f1b.y;
            a.x += w2 * f2a.x; a.y += w2 * f2a.y; a.z += w2 * f2b.x; a.w += w2 * f2b.y;
            a.x += w3 * f3a.x; a.y += w3 * f3a.y; a.z += w3 * f3b.x; a.w += w3 * f3b.y;
        }
        for (; q < L; q++) {
            int si = g_col[p0 + q];
            float w = inCap ? wbuf[wid][q] : g_ew[(size_t)head * ETOT + p0 + q];
            uint2 u = *reinterpret_cast<const uint2*>(xb + (size_t)si * 256 + lane * 4);
            float2 fa = __bfloat1622float2(*reinterpret_cast<__nv_bfloat162*>(&u.x));
            float2 fb = __bfloat1622float2(*reinterpret_cast<__nv_bfloat162*>(&u.y));
            a.x += w * fa.x; a.y += w * fa.y; a.z += w * fb.x; a.w += w * fb.y;
        }
    }

    if (active && head == 1) {
        *reinterpret_cast<float4*>(&stage[pairId][lane * 4]) =
            make_float4(a.x * inv, a.y * inv, a.z * inv, a.w * inv);
    }
    __syncthreads();
    if (active && head == 0) {
        float4 v1 = *reinterpret_cast<const float4*>(&stage[pairId][lane * 4]);
        float4 bv = reinterpret_cast<const float4*>(bias)[lane];
        float4 o;
        o.x = 0.5f * (a.x * inv + v1.x) + bv.x;
        o.y = 0.5f * (a.y * inv + v1.y) + bv.y;
        o.z = 0.5f * (a.z * inv + v1.z) + bv.z;
        o.w = 0.5f * (a.w * inv + v1.w) + bv.w;
        if (out)
            *reinterpret_cast<float4*>(out + (size_t)node * DIM + lane * 4) = o;
        int k = lane * 4;
        int base = node * 128 + (k & ~31) + ((k & 31) >> 2);
        g_hT[base + 0]  = f2tf32(o.x);
        g_hT[base + 8]  = f2tf32(o.y);
        g_hT[base + 16] = f2tf32(o.z);
        g_hT[base + 24] = f2tf32(o.w);
    }
}

// ---------------- Set2Set ----------------------------------------------------
// coalesced interleaved-4 weight layout: wi4[kq*512 + tid] (float4)
__global__ void __launch_bounds__(512) k_lstm(const float* __restrict__ bih,
                                              const float* __restrict__ bhh) {
    int b = blockIdx.x;
    int tid = threadIdx.x;
    __shared__ float qs[256];
    __shared__ float hs[128];
    __shared__ float gates[512];
    if (tid < 256) qs[tid] = g_qstar[b * 256 + tid];
    else if (tid < 384) hs[tid - 256] = g_lq[b * 128 + (tid - 256)];
    __syncthreads();
    float acc = bih[tid] + bhh[tid];
    const float4* wi4 = reinterpret_cast<const float4*>(g_WihT);
#pragma unroll 8
    for (int kq = 0; kq < 64; kq++) {
        float4 w = wi4[kq * 512 + tid];
        acc += w.x * qs[kq * 4] + w.y * qs[kq * 4 + 1]
             + w.z * qs[kq * 4 + 2] + w.w * qs[kq * 4 + 3];
    }
    const float4* wh4 = reinterpret_cast<const float4*>(g_WhhT);
#pragma unroll 8
    for (int kq = 0; kq < 32; kq++) {
        float4 w = wh4[kq * 512 + tid];
        acc += w.x * hs[kq * 4] + w.y * hs[kq * 4 + 1]
             + w.z * hs[kq * 4 + 2] + w.w * hs[kq * 4 + 3];
    }
    gates[tid] = acc;
    __syncthreads();
    if (tid < 128) {
        float gi = 1.f / (1.f + __expf(-gates[tid]));
        float gf = 1.f / (1.f + __expf(-gates[128 + tid]));
        float gg = tanhf(gates[256 + tid]);
        float go = 1.f / (1.f + __expf(-gates[384 + tid]));
        float c2 = gf * g_lc[b * 128 + tid] + gi * gg;
        float q = go * tanhf(c2);
        g_lc[b * 128 + tid] = c2;
        g_lq[b * 128 + tid] = q;
        g_qstar[b * 256 + tid] = q;
    }
}

// fused attention-pool step (512 threads / 16 warps)
__global__ void __launch_bounds__(512) k_s2s(const float* __restrict__ h) {
    int b = blockIdx.x;
    int tid = threadIdx.x;
    int wid = tid >> 5, lane = tid & 31;
    int p0 = g_bptr[b];
    int L = g_bptr[b + 1] - p0;

    __shared__ float q[128];
    __shared__ float se[1024];
    __shared__ float red[40];
    __shared__ float racc[512];

    if (tid < 128) q[tid] = g_lq[b * 128 + tid];
    __syncthreads();

    float4 qv = reinterpret_cast<const float4*>(q)[lane];
    for (int i = wid; i < L; i += 16) {
        float4 hv = reinterpret_cast<const float4*>(h + (size_t)(p0 + i) * 128)[lane];
        float r = hv.x * qv.x + hv.y * qv.y + hv.z * qv.z + hv.w * qv.w;
        r = wred_sum(r);
        if (lane == 0) se[i] = r;
    }
    __syncthreads();

    float m = -1e30f;
    for (int i = tid; i < L; i += 512) m = fmaxf(m, se[i]);
#pragma unroll
    for (int o = 16; o > 0; o >>= 1) m = fmaxf(m, __shfl_xor_sync(0xffffffffu, m, o));
    if (lane == 0) red[wid] = m;
    __syncthreads();
    if (tid == 0) {
        float mm = red[0];
        for (int w = 1; w < 16; w++) mm = fmaxf(mm, red[w]);
        red[32] = mm;
    }
    __syncthreads();
    m = red[32];

    float s = 0.f;
    for (int i = tid; i < L; i += 512) {
        float w = __expf(se[i] - m);
        se[i] = w;
        s += w;
    }
    s = wred_sum(s);
    if (lane == 0) red[wid] = s;
    __syncthreads();
    if (tid == 0) {
        float ss = 0.f;
        for (int w = 0; w < 16; w++) ss += red[w];
        red[33] = 1.f / (ss + 1e-16f);
    }
    __syncthreads();
    float inv = red[33];

    int d = tid & 127, part = tid >> 7;
    float acc = 0.f;
    for (int i = part; i < L; i += 4)
        acc += se[i] * h[(size_t)(p0 + i) * 128 + d];
    racc[tid] = acc;
    __syncthreads();
    if (tid < 128)
        g_qstar[b * 256 + 128 + tid] =
            (racc[tid] + racc[128 + tid] + racc[256 + tid] + racc[384 + tid]) * inv;
}

// ---------------- final MLP --------------------------------------------------
__global__ void __launch_bounds__(128) k_mlp(const float* __restrict__ W1, const float* __restrict__ b1,
                                             const float* __restrict__ W2, const float* __restrict__ b2,
                                             float* __restrict__ out) {
    int b = blockIdx.x;
    int j = threadIdx.x;
    __shared__ float qs[256];
    __shared__ float hid[128];
    qs[j] = g_qstar[b * 256 + j];
    qs[128 + j] = g_qstar[b * 256 + 128 + j];
    __syncthreads();
    float acc = b1[j];
#pragma unroll 8
    for (int k = 0; k < 256; k++) acc += qs[k] * W1[k * 128 + j];
    hid[j] = fmaxf(acc, 0.f);
    __syncthreads();
    float acc2 = b2[j];
#pragma unroll 8
    for (int k = 0; k < 128; k++) acc2 += hid[k] * W2[k * 128 + j];
    out[b * 128 + j] = acc2;
}

// ---------------- launch -----------------------------------------------------
extern "C" void kernel_launch(void* const* d_in, const int* in_sizes, int n_in,
                              void* d_out, int out_size) {
    const float* x        = (const float*)d_in[0];
    const int*   ei       = (const int*)d_in[1];     // int64 inputs delivered as int32
    const int*   batch    = (const int*)d_in[3];
    const float* gat_W    = (const float*)d_in[4];
    const float* att_src  = (const float*)d_in[5];
    const float* att_dst  = (const float*)d_in[6];
    const float* gat_bias = (const float*)d_in[7];
    const float* Wih      = (const float*)d_in[8];
    const float* Whh      = (const float*)d_in[9];
    const float* bih      = (const float*)d_in[10];
    const float* bhh      = (const float*)d_in[11];
    const float* W1       = (const float*)d_in[12];
    const float* b1       = (const float*)d_in[13];
    const float* W2       = (const float*)d_in[14];
    const float* b2       = (const float*)d_in[15];
    float*       out      = (float*)d_out;

    const int* src = ei;
    const int* dst = ei + NEDGES;

    float* hA = nullptr;
    float* hB = nullptr;
    cudaGetSymbolAddress((void**)&hA, g_hA);
    cudaGetSymbolAddress((void**)&hB, g_hB);

    const int aggBlocks = (NNODES + 3) / 4;
    dim3 gg(NPAD / 128, 2);

    // order keeps k_gemm_att at launch #4 (ncu fixed-window profiling)
    k_init_h<<<(NPAD * (DIM / 4) + 255) / 256, 256>>>(x);
    k_misc<<<512, 256>>>(gat_W, Wih, Whh);
    k_hist<<<(NEDGES + 255) / 256, 256>>>(dst);
    k_gemm_att<<<gg, 256>>>(att_src, att_dst, 32);        // conv0 GEMM: 9 nonzero feats
    k_scan1<<<NCHUNK, 256>>>();
    k_scan2<<<1, 256>>>();
    k_scan3<<<NCHUNK, 256>>>();
    k_scatter<<<(ETOT + 255) / 256, 256>>>(src, dst);
    k_bptr<<<1, 256>>>(batch);

    float* cur = hA;
    float* nxt = hB;
    for (int c = 0; c < 3; c++) {
        if (c > 0) k_gemm_att<<<gg, 256>>>(att_src, att_dst, 128);
        k_aggregate<<<aggBlocks, 256>>>(gat_bias, (c == 2) ? nxt : nullptr);
        float* t = cur; cur = nxt; nxt = t;
    }

    for (int s = 0; s < 3; s++) {
        k_lstm<<<BATCH, 512>>>(bih, bhh);
        k_s2s<<<BATCH, 512>>>(cur);
    }

    k_mlp<<<BATCH, 128>>>(W1, b1, W2, b2, out);
}

// round 17
// speedup vs baseline: 1.1972x; 1.0086x over previous
#include <cuda_runtime.h>
#include <cuda_bf16.h>
#include <math.h>

#define NNODES 50000
#define NPAD   50048              // 391 * 128
#define NEDGES 800000
#define ETOT   (NEDGES + NNODES)  // edges + self loops
#define BATCH  128
#define DIM    128
#define NEG_SLOPE 0.2f
#define NCHUNK 196                // ceil(50000/256)
#define CAP    128                // smem weight stash per warp

// pair-packed word index within a 128-k row (fragment order for tf32 mma)
#define WIDX(k) (((k) & ~31) + (((k) & 3) << 3) + (((k) & 31) >> 2))

// ---------------- scratch (device globals) ----------------------------------
__device__ float    g_hA[NPAD * DIM];
__device__ float    g_hB[NPAD * DIM];
__device__ unsigned g_hT[NPAD * DIM];          // tf32 h, pair-packed per row
__device__ unsigned g_WT[2 * DIM * DIM];       // tf32 W, [n][k] pair-packed
__device__ __nv_bfloat16 g_xlh[(size_t)NPAD * 2 * DIM];  // bf16 xl (gather operand)
__device__ float    g_asrc[NPAD * 2];
__device__ float    g_adst[NPAD * 2];
__device__ int      g_deg[NNODES];
__device__ int      g_rowptr[NNODES + 1];
__device__ int      g_wp[NNODES];
__device__ int      g_col[ETOT];
__device__ float    g_ew[(size_t)2 * ETOT];    // [head][edge] fallback
__device__ int      g_bsum[256];
__device__ int      g_bbase[256];
__device__ int      g_bptr[BATCH + 1];
__device__ float    g_WihT[4 * DIM * 2 * DIM]; // interleaved-4: [kq][j][4]
__device__ float    g_WhhT[4 * DIM * DIM];     // interleaved-4: [kq][j][4]

// ---------------- helpers ---------------------------------------------------
__device__ __forceinline__ float wred_sum(float v) {
#pragma unroll
    for (int o = 16; o > 0; o >>= 1) v += __shfl_xor_sync(0xffffffffu, v, o);
    return v;
}
__device__ __forceinline__ float lrelu(float v) { return v > 0.f ? v : NEG_SLOPE * v; }
__device__ __forceinline__ unsigned f2tf32(float f) {
    unsigned u;
    asm("cvt.rna.tf32.f32 %0, %1;" : "=r"(u) : "f"(f));
    return u;
}

// ---------------- input padding + deg init + tf32 pair-packed copy -----------
__global__ void k_init_h(const float* __restrict__ x) {
    int i = blockIdx.x * blockDim.x + threadIdx.x;  // float4 index
    if (i >= NPAD * (DIM / 4)) return;
    int n = i >> 5;
    int k = (i & 31) * 4;
    float4 v = make_float4(0.f, 0.f, 0.f, 0.f);
    if (n < NNODES) {
        if (k + 0 < 9) v.x = x[n * 9 + k + 0];
        if (k + 1 < 9) v.y = x[n * 9 + k + 1];
        if (k + 2 < 9) v.z = x[n * 9 + k + 2];
        if (k + 3 < 9) v.w = x[n * 9 + k + 3];
        if ((i & 31) == 0) g_deg[n] = 1;  // self loop
    }
    reinterpret_cast<float4*>(g_hA)[i] = v;
    int base = n * 128 + (k & ~31) + ((k & 31) >> 2);   // k%4==0
    g_hT[base + 0]  = f2tf32(v.x);
    g_hT[base + 8]  = f2tf32(v.y);
    g_hT[base + 16] = f2tf32(v.z);
    g_hT[base + 24] = f2tf32(v.w);
}

// W tf32 convert + LSTM weight interleave (merged elementwise setup)
__global__ void k_misc(const float* __restrict__ W,
                       const float* __restrict__ Wih,
                       const float* __restrict__ Whh) {
    int i = blockIdx.x * blockDim.x + threadIdx.x;
    if (i < DIM * 2 * DIM) {                    // gat_W -> tf32 pair-packed
        int k = i >> 8;
        int n = i & 255;
        g_WT[n * 128 + WIDX(k)] = f2tf32(W[i]);
    }
    if (i < 4 * DIM * 2 * DIM) {                // Wih [512][256] -> [kq][j][4]
        int j = i >> 8;
        int k = i & 255;
        g_WihT[(k >> 2) * 2048 + j * 4 + (k & 3)] = Wih[i];
    }
    if (i < 4 * DIM * DIM) {                    // Whh [512][128] -> [kq][j][4]
        int j = i >> 7;
        int k = i & 127;
        g_WhhT[(k >> 2) * 2048 + j * 4 + (k & 3)] = Whh[i];
    }
}

// ---------------- CSR build --------------------------------------------------
__global__ void k_hist(const int* __restrict__ dst) {
    int e = blockIdx.x * blockDim.x + threadIdx.x;
    if (e < NEDGES) atomicAdd(&g_deg[dst[e]], 1);
}
__global__ void __launch_bounds__(256) k_scan1() {
    __shared__ int ss[256];
    int t = threadIdx.x;
    int idx = blockIdx.x * 256 + t;
    ss[t] = (idx < NNODES) ? g_deg[idx] : 0;
    __syncthreads();
    for (int off = 128; off > 0; off >>= 1) {
        if (t < off) ss[t] += ss[t + off];
        __syncthreads();
    }
    if (t == 0) g_bsum[blockIdx.x] = ss[0];
}
__global__ void __launch_bounds__(256) k_scan2() {
    __shared__ int ss[256];
    int t = threadIdx.x;
    int v = (t < NCHUNK) ? g_bsum[t] : 0;
    ss[t] = v;
    __syncthreads();
    for (int off = 1; off < 256; off <<= 1) {
        int x = (t >= off) ? ss[t - off] : 0;
        __syncthreads();
        ss[t] += x;
        __syncthreads();
    }
    if (t < NCHUNK) g_bbase[t] = ss[t] - v;  // exclusive
}
__global__ void __launch_bounds__(256) k_scan3() {
    __shared__ int ss[256];
    int t = threadIdx.x;
    int idx = blockIdx.x * 256 + t;
    int v = (idx < NNODES) ? g_deg[idx] : 0;
    ss[t] = v;
    __syncthreads();
    for (int off = 1; off < 256; off <<= 1) {
        int x = (t >= off) ? ss[t - off] : 0;
        __syncthreads();
        ss[t] += x;
        __syncthreads();
    }
    if (idx < NNODES) {
        int r = g_bbase[blockIdx.x] + ss[t] - v;
        g_rowptr[idx] = r;
        g_wp[idx] = r;
    }
    if (idx == 0) g_rowptr[NNODES] = ETOT;
}
__global__ void k_scatter(const int* __restrict__ src, const int* __restrict__ dst) {
    int i = blockIdx.x * blockDim.x + threadIdx.x;
    if (i < NEDGES) {
        int d = dst[i];
        int p = atomicAdd(&g_wp[d], 1);
        g_col[p] = src[i];
    } else if (i < ETOT) {
        int n = i - NEDGES;
        int p = atomicAdd(&g_wp[n], 1);
        g_col[p] = n;
    }
}
__global__ void k_bptr(const int* __restrict__ batch) {
    int b = threadIdx.x;
    if (b > BATCH) return;
    if (b == BATCH) { g_bptr[BATCH] = NNODES; return; }
    int lo = 0, hi = NNODES;
    while (lo < hi) {
        int mid = (lo + hi) >> 1;
        if (batch[mid] < b) lo = mid + 1; else hi = mid;
    }
    g_bptr[b] = lo;
}

// ---- tf32 MMA GEMM + fused attention dots -----------------------------------
__global__ void __launch_bounds__(256) k_gemm_att(const float* __restrict__ att_src,
                                                  const float* __restrict__ att_dst,
                                                  int keff) {
    __shared__ unsigned Asw[128 * 34];    // 17 uint2 per row + pad
    __shared__ unsigned Bsw[128 * 34];
    __shared__ float sAs[128], sAd[128];

    const int tid = threadIdx.x;
    const int bm = blockIdx.x * 128;
    const int head = blockIdx.y;         // 0 or 1
    const int bn = head * 128;
    const int wid = tid >> 5, lane = tid & 31;
    const int wm = wid >> 2, wn = wid & 3;   // warp grid 2 x 4
    const int g = lane >> 2, tig = lane & 3;

    if (tid < 128) { sAs[tid] = 0.f; sAd[tid] = 0.f; }

    float c[4][4][4];
#pragma unroll
    for (int mt = 0; mt < 4; mt++)
#pragma unroll
        for (int nt = 0; nt < 4; nt++)
#pragma unroll
            for (int j = 0; j < 4; j++) c[mt][nt][j] = 0.f;

    for (int k0 = 0; k0 < keff; k0 += 32) {
#pragma unroll
        for (int i = 0; i < 4; i++) {
            int slot = tid + i * 256;
            int r = slot >> 3, q4 = (slot & 7) * 4;
            uint4 va = *reinterpret_cast<const uint4*>(g_hT + (size_t)(bm + r) * 128 + k0 + q4);
            uint2* pa = reinterpret_cast<uint2*>(&Asw[r * 34 + q4]);
            pa[0] = make_uint2(va.x, va.y);
            pa[1] = make_uint2(va.z, va.w);
            uint4 vb = *reinterpret_cast<const uint4*>(g_WT + (size_t)(bn + r) * 128 + k0 + q4);
            uint2* pb = reinterpret_cast<uint2*>(&Bsw[r * 34 + q4]);
            pb[0] = make_uint2(vb.x, vb.y);
            pb[1] = make_uint2(vb.z, vb.w);
        }
        __syncthreads();
        const uint2* AsP = reinterpret_cast<const uint2*>(Asw);
        const uint2* BsP = reinterpret_cast<const uint2*>(Bsw);
#pragma unroll
        for (int ks = 0; ks < 4; ks++) {
            unsigned af[4][4], bf[4][2];
#pragma unroll
            for (int mt = 0; mt < 4; mt++) {
                int r0 = wm * 64 + mt * 16 + g;
                uint2 lo = AsP[r0 * 17 + tig * 4 + ks];
                uint2 hi = AsP[(r0 + 8) * 17 + tig * 4 + ks];
                af[mt][0] = lo.x; af[mt][1] = hi.x;
                af[mt][2] = lo.y; af[mt][3] = hi.y;
            }
#pragma unroll
            for (int nt = 0; nt < 4; nt++) {
                int c0 = wn * 32 + nt * 8 + g;
                uint2 bp = BsP[c0 * 17 + tig * 4 + ks];
                bf[nt][0] = bp.x; bf[nt][1] = bp.y;
            }
#pragma unroll
            for (int mt = 0; mt < 4; mt++)
#pragma unroll
                for (int nt = 0; nt < 4; nt++) {
                    asm volatile(
                        "mma.sync.aligned.m16n8k8.row.col.f32.tf32.tf32.f32 "
                        "{%0,%1,%2,%3}, {%4,%5,%6,%7}, {%8,%9}, {%0,%1,%2,%3};"
                        : "+f"(c[mt][nt][0]), "+f"(c[mt][nt][1]),
                          "+f"(c[mt][nt][2]), "+f"(c[mt][nt][3])
                        : "r"(af[mt][0]), "r"(af[mt][1]), "r"(af[mt][2]), "r"(af[mt][3]),
                          "r"(bf[nt][0]), "r"(bf[nt][1]));
                }
        }
        __syncthreads();
    }

    float asr[8], adr[8];
#pragma unroll
    for (int nt = 0; nt < 4; nt++) {
#pragma unroll
        for (int j = 0; j < 2; j++) {
            int col = wn * 32 + nt * 8 + tig * 2 + j;
            asr[nt * 2 + j] = att_src[head * 128 + col];
            adr[nt * 2 + j] = att_dst[head * 128 + col];
        }
    }

#pragma unroll
    for (int mt = 0; mt < 4; mt++) {
#pragma unroll
        for (int half = 0; half < 2; half++) {
            int lr = wm * 64 + mt * 16 + g + half * 8;
            int row = bm + lr;
            float ds = 0.f, dd = 0.f;
#pragma unroll
            for (int nt = 0; nt < 4; nt++) {
                float v0 = c[mt][nt][half * 2];
                float v1 = c[mt][nt][half * 2 + 1];
                int col = bn + wn * 32 + nt * 8 + tig * 2;
                *reinterpret_cast<__nv_bfloat162*>(g_xlh + (size_t)row * 256 + col) =
                    __floats2bfloat162_rn(v0, v1);
                ds += v0 * asr[nt * 2] + v1 * asr[nt * 2 + 1];
                dd += v0 * adr[nt * 2] + v1 * adr[nt * 2 + 1];
            }
            ds += __shfl_xor_sync(0xffffffffu, ds, 1);
            ds += __shfl_xor_sync(0xffffffffu, ds, 2);
            dd += __shfl_xor_sync(0xffffffffu, dd, 1);
            dd += __shfl_xor_sync(0xffffffffu, dd, 2);
            if (tig == 0) {
                atomicAdd(&sAs[lr], ds);
                atomicAdd(&sAd[lr], dd);
            }
        }
    }
    __syncthreads();
    if (tid < 128) {
        g_asrc[(size_t)(bm + tid) * 2 + head] = sAs[tid];
        g_adst[(size_t)(bm + tid) * 2 + head] = sAd[tid];
    }
}

// ------- softmax-aggregate: warp per (node, head); 4-deep bf16 gather --------
__global__ void __launch_bounds__(256) k_aggregate(const float* __restrict__ bias,
                                                   float* __restrict__ out) {
    __shared__ float wbuf[8][CAP];
    __shared__ float stage[4][DIM];

    const int tid = threadIdx.x;
    const int wid = tid >> 5, lane = tid & 31;
    const int pairId = wid >> 1;
    const int head = wid & 1;
    const int node = blockIdx.x * 4 + pairId;
    const bool active = node < NNODES;

    int p0 = 0, L = 0;
    float ad = 0.f;
    if (active) {
        p0 = g_rowptr[node];
        L = g_rowptr[node + 1] - p0;
        ad = g_adst[node * 2 + head];
    }
    const bool inCap = (L <= CAP);

    float s = 0.f;
    if (active) {
        if (inCap) {
            for (int q = lane; q < L; q += 32) {
                int si = g_col[p0 + q];
                float e = __expf(lrelu(g_asrc[si * 2 + head] + ad));
                wbuf[wid][q] = e;
                s += e;
            }
        } else {
            for (int q = lane; q < L; q += 32) {
                int si = g_col[p0 + q];
                float e = __expf(lrelu(g_asrc[si * 2 + head] + ad));
                g_ew[(size_t)head * ETOT + p0 + q] = e;
                s += e;
            }
        }
        s = wred_sum(s);
    }
    __syncwarp();
    float inv = 1.f / (s + 1e-16f);

    float4 a = make_float4(0.f, 0.f, 0.f, 0.f);
    if (active) {
        const __nv_bfloat16* xb = g_xlh + head * 128;
        int q = 0;
        for (; q + 4 <= L; q += 4) {
            int si0 = g_col[p0 + q + 0];
            int si1 = g_col[p0 + q + 1];
            int si2 = g_col[p0 + q + 2];
            int si3 = g_col[p0 + q + 3];
            uint2 u0 = *reinterpret_cast<const uint2*>(xb + (size_t)si0 * 256 + lane * 4);
            uint2 u1 = *reinterpret_cast<const uint2*>(xb + (size_t)si1 * 256 + lane * 4);
            uint2 u2 = *reinterpret_cast<const uint2*>(xb + (size_t)si2 * 256 + lane * 4);
            uint2 u3 = *reinterpret_cast<const uint2*>(xb + (size_t)si3 * 256 + lane * 4);
            float w0, w1, w2, w3;
            if (inCap) {
                w0 = wbuf[wid][q + 0]; w1 = wbuf[wid][q + 1];
                w2 = wbuf[wid][q + 2]; w3 = wbuf[wid][q + 3];
            } else {
                w0 = g_ew[(size_t)head * ETOT + p0 + q + 0];
                w1 = g_ew[(size_t)head * ETOT + p0 + q + 1];
                w2 = g_ew[(size_t)head * ETOT + p0 + q + 2];
                w3 = g_ew[(size_t)head * ETOT + p0 + q + 3];
            }
            float2 f0a = __bfloat1622float2(*reinterpret_cast<__nv_bfloat162*>(&u0.x));
            float2 f0b = __bfloat1622float2(*reinterpret_cast<__nv_bfloat162*>(&u0.y));
            float2 f1a = __bfloat1622float2(*reinterpret_cast<__nv_bfloat162*>(&u1.x));
            float2 f1b = __bfloat1622float2(*reinterpret_cast<__nv_bfloat162*>(&u1.y));
            float2 f2a = __bfloat1622float2(*reinterpret_cast<__nv_bfloat162*>(&u2.x));
            float2 f2b = __bfloat1622float2(*reinterpret_cast<__nv_bfloat162*>(&u2.y));
            float2 f3a = __bfloat1622float2(*reinterpret_cast<__nv_bfloat162*>(&u3.x));
            float2 f3b = __bfloat1622float2(*reinterpret_cast<__nv_bfloat162*>(&u3.y));
            a.x += w0 * f0a.x; a.y += w0 * f0a.y; a.z += w0 * f0b.x; a.w += w0 * f0b.y;
            a.x += w1 * f1a.x; a.y += w1 * f1a.y; a.z += w1 * f1b.x; a.w += w1 * f1b.y;
            a.x += w2 * f2a.x; a.y += w2 * f2a.y; a.z += w2 * f2b.x; a.w += w2 * f2b.y;
            a.x += w3 * f3a.x; a.y += w3 * f3a.y; a.z += w3 * f3b.x; a.w += w3 * f3b.y;
        }
        for (; q < L; q++) {
            int si = g_col[p0 + q];
            float w = inCap ? wbuf[wid][q] : g_ew[(size_t)head * ETOT + p0 + q];
            uint2 u = *reinterpret_cast<const uint2*>(xb + (size_t)si * 256 + lane * 4);
            float2 fa = __bfloat1622float2(*reinterpret_cast<__nv_bfloat162*>(&u.x));
            float2 fb = __bfloat1622float2(*reinterpret_cast<__nv_bfloat162*>(&u.y));
            a.x += w * fa.x; a.y += w * fa.y; a.z += w * fb.x; a.w += w * fb.y;
        }
    }

    if (active && head == 1) {
        *reinterpret_cast<float4*>(&stage[pairId][lane * 4]) =
            make_float4(a.x * inv, a.y * inv, a.z * inv, a.w * inv);
    }
    __syncthreads();
    if (active && head == 0) {
        float4 v1 = *reinterpret_cast<const float4*>(&stage[pairId][lane * 4]);
        float4 bv = reinterpret_cast<const float4*>(bias)[lane];
        float4 o;
        o.x = 0.5f * (a.x * inv + v1.x) + bv.x;
        o.y = 0.5f * (a.y * inv + v1.y) + bv.y;
        o.z = 0.5f * (a.z * inv + v1.z) + bv.z;
        o.w = 0.5f * (a.w * inv + v1.w) + bv.w;
        if (out)
            *reinterpret_cast<float4*>(out + (size_t)node * DIM + lane * 4) = o;
        int k = lane * 4;
        int base = node * 128 + (k & ~31) + ((k & 31) >> 2);
        g_hT[base + 0]  = f2tf32(o.x);
        g_hT[base + 8]  = f2tf32(o.y);
        g_hT[base + 16] = f2tf32(o.z);
        g_hT[base + 24] = f2tf32(o.w);
    }
}

// ---- fused Set2Set (3 steps) + MLP: one block per batch segment -------------
__global__ void __launch_bounds__(512) k_tail(const float* __restrict__ bih,
                                              const float* __restrict__ bhh,
                                              const float* __restrict__ W1,
                                              const float* __restrict__ b1,
                                              const float* __restrict__ W2,
                                              const float* __restrict__ b2,
                                              const float* __restrict__ h,
                                              float* __restrict__ out) {
    int b = blockIdx.x;
    int tid = threadIdx.x;
    int wid = tid >> 5, lane = tid & 31;
    int p0 = g_bptr[b];
    int L = g_bptr[b + 1] - p0;

    __shared__ float qs[256];     // q_star
    __shared__ float hq[128];     // lstm q (hidden)
    __shared__ float cs[128];     // lstm cell
    __shared__ float gates[512];
    __shared__ float se[1024];
    __shared__ float red[40];
    __shared__ float racc[512];

    if (tid < 256) qs[tid] = 0.f;
    if (tid < 128) { hq[tid] = 0.f; cs[tid] = 0.f; }
    __syncthreads();

    const float4* wi4 = reinterpret_cast<const float4*>(g_WihT);
    const float4* wh4 = reinterpret_cast<const float4*>(g_WhhT);

    for (int step = 0; step < 3; step++) {
        // ---- LSTM gates (coalesced interleaved-4 weights) ----
        float acc = bih[tid] + bhh[tid];
#pragma unroll 8
        for (int kq = 0; kq < 64; kq++) {
            float4 w = wi4[kq * 512 + tid];
            acc += w.x * qs[kq * 4] + w.y * qs[kq * 4 + 1]
                 + w.z * qs[kq * 4 + 2] + w.w * qs[kq * 4 + 3];
        }
#pragma unroll 8
        for (int kq = 0; kq < 32; kq++) {
            float4 w = wh4[kq * 512 + tid];
            acc += w.x * hq[kq * 4] + w.y * hq[kq * 4 + 1]
                 + w.z * hq[kq * 4 + 2] + w.w * hq[kq * 4 + 3];
        }
        gates[tid] = acc;
        __syncthreads();
        if (tid < 128) {
            float gi = 1.f / (1.f + __expf(-gates[tid]));
            float gf = 1.f / (1.f + __expf(-gates[128 + tid]));
            float gg = tanhf(gates[256 + tid]);
            float go = 1.f / (1.f + __expf(-gates[384 + tid]));
            float c2 = gf * cs[tid] + gi * gg;
            float q = go * tanhf(c2);
            cs[tid] = c2;
            hq[tid] = q;
        }
        __syncthreads();

        // ---- e per node (16 warps strided) ----
        float4 qv = reinterpret_cast<const float4*>(hq)[lane];
        for (int i = wid; i < L; i += 16) {
            float4 hv = reinterpret_cast<const float4*>(h + (size_t)(p0 + i) * 128)[lane];
            float r = hv.x * qv.x + hv.y * qv.y + hv.z * qv.z + hv.w * qv.w;
            r = wred_sum(r);
            if (lane == 0) se[i] = r;
        }
        __syncthreads();

        // ---- block max ----
        float m = -1e30f;
        for (int i = tid; i < L; i += 512) m = fmaxf(m, se[i]);
#pragma unroll
        for (int o = 16; o > 0; o >>= 1) m = fmaxf(m, __shfl_xor_sync(0xffffffffu, m, o));
        if (lane == 0) red[wid] = m;
        __syncthreads();
        if (tid == 0) {
            float mm = red[0];
            for (int w = 1; w < 16; w++) mm = fmaxf(mm, red[w]);
            red[32] = mm;
        }
        __syncthreads();
        m = red[32];

        // ---- exp + sum (weights stored in se) ----
        float s = 0.f;
        for (int i = tid; i < L; i += 512) {
            float w = __expf(se[i] - m);
            se[i] = w;
            s += w;
        }
        s = wred_sum(s);
        if (lane == 0) red[wid] = s;
        __syncthreads();
        if (tid == 0) {
            float ss = 0.f;
            for (int w = 0; w < 16; w++) ss += red[w];
            red[33] = 1.f / (ss + 1e-16f);
        }
        __syncthreads();
        float inv = red[33];

        // ---- weighted reduce: 4-way node split, one dim per thread ----
        int d = tid & 127, part = tid >> 7;
        float acc2 = 0.f;
        for (int i = part; i < L; i += 4)
            acc2 += se[i] * h[(size_t)(p0 + i) * 128 + d];
        racc[tid] = acc2;
        __syncthreads();
        if (tid < 128) {
            qs[128 + tid] =
                (racc[tid] + racc[128 + tid] + racc[256 + tid] + racc[384 + tid]) * inv;
            qs[tid] = hq[tid];
        }
        __syncthreads();
    }

    // ---- final MLP row b ----
    if (tid < 128) {
        int j = tid;
        float acc = b1[j];
#pragma unroll 8
        for (int k = 0; k < 256; k++) acc += qs[k] * W1[k * 128 + j];
        se[j] = fmaxf(acc, 0.f);
    }
    __syncthreads();
    if (tid < 128) {
        int j = tid;
        float acc2 = b2[j];
#pragma unroll 8
        for (int k = 0; k < 128; k++) acc2 += se[k] * W2[k * 128 + j];
        out[b * 128 + j] = acc2;
    }
}

// ---------------- launch -----------------------------------------------------
extern "C" void kernel_launch(void* const* d_in, const int* in_sizes, int n_in,
                              void* d_out, int out_size) {
    const float* x        = (const float*)d_in[0];
    const int*   ei       = (const int*)d_in[1];     // int64 inputs delivered as int32
    const int*   batch    = (const int*)d_in[3];
    const float* gat_W    = (const float*)d_in[4];
    const float* att_src  = (const float*)d_in[5];
    const float* att_dst  = (const float*)d_in[6];
    const float* gat_bias = (const float*)d_in[7];
    const float* Wih      = (const float*)d_in[8];
    const float* Whh      = (const float*)d_in[9];
    const float* bih      = (const float*)d_in[10];
    const float* bhh      = (const float*)d_in[11];
    const float* W1       = (const float*)d_in[12];
    const float* b1       = (const float*)d_in[13];
    const float* W2       = (const float*)d_in[14];
    const float* b2       = (const float*)d_in[15];
    float*       out      = (float*)d_out;

    const int* src = ei;
    const int* dst = ei + NEDGES;

    float* hA = nullptr;
    float* hB = nullptr;
    cudaGetSymbolAddress((void**)&hA, g_hA);
    cudaGetSymbolAddress((void**)&hB, g_hB);

    const int aggBlocks = (NNODES + 3) / 4;
    dim3 gg(NPAD / 128, 2);

    // order keeps k_gemm_att at launch #4 (ncu fixed-window profiling)
    k_init_h<<<(NPAD * (DIM / 4) + 255) / 256, 256>>>(x);
    k_misc<<<512, 256>>>(gat_W, Wih, Whh);
    k_hist<<<(NEDGES + 255) / 256, 256>>>(dst);
    k_gemm_att<<<gg, 256>>>(att_src, att_dst, 32);        // conv0 GEMM: 9 nonzero feats
    k_scan1<<<NCHUNK, 256>>>();
    k_scan2<<<1, 256>>>();
    k_scan3<<<NCHUNK, 256>>>();
    k_scatter<<<(ETOT + 255) / 256, 256>>>(src, dst);
    k_bptr<<<1, 256>>>(batch);

    float* cur = hA;
    float* nxt = hB;
    for (int c = 0; c < 3; c++) {
        if (c > 0) k_gemm_att<<<gg, 256>>>(att_src, att_dst, 128);
        k_aggregate<<<aggBlocks, 256>>>(gat_bias, (c == 2) ? nxt : nullptr);
        float* t = cur; cur = nxt; nxt = t;
    }

    k_tail<<<BATCH, 512>>>(bih, bhh, W1, b1, W2, b2, cur, out);
}